// round 4
// baseline (speedup 1.0000x reference)
#include <cuda_runtime.h>
#include <cooperative_groups.h>
#include <math.h>

namespace cg = cooperative_groups;

#define VOCAB 32000
#define HALF  16000
#define Q4    (HALF / 4)     // 4000 float4 per CTA
#define KNN   32
#define NT    512
#define PER_T 8              // ceil(4000/512)

__device__ __forceinline__ float warp_max(float v) {
    #pragma unroll
    for (int o = 16; o > 0; o >>= 1) v = fmaxf(v, __shfl_xor_sync(0xFFFFFFFFu, v, o));
    return v;
}
__device__ __forceinline__ float warp_sum(float v) {
    #pragma unroll
    for (int o = 16; o > 0; o >>= 1) v += __shfl_xor_sync(0xFFFFFFFFu, v, o);
    return v;
}

__global__ __launch_bounds__(NT, 2) __cluster_dims__(2, 1, 1)
void knn_model_kernel(const float* __restrict__ logits,
                      const int*   __restrict__ optor_vals,
                      const float* __restrict__ optor_dists,
                      const int*   __restrict__ const_vals,
                      const float* __restrict__ const_dists,
                      const int*   __restrict__ prev_words,
                      const float* __restrict__ optor_lamda,
                      const float* __restrict__ const_lamda,
                      const float* __restrict__ optor_temp,
                      const float* __restrict__ const_temp,
                      float*       __restrict__ out)
{
    __shared__ float red_sum[16];
    __shared__ float partial;                 // this CTA's partial exp-sum
    __shared__ float gsum_sh;

    cg::cluster_group cluster = cg::this_cluster();

    const int r    = blockIdx.x >> 1;         // row in [0, B*S)
    const int h    = blockIdx.x & 1;          // half index (== cluster rank)
    const int tid  = threadIdx.x;
    const int wid  = tid >> 5;
    const int lane = tid & 31;

    const float4* __restrict__ l4 = (const float4*)(logits + (size_t)r * VOCAB + (size_t)h * HALF);
    float4* __restrict__ o4  = (float4*)(out + (size_t)r * VOCAB + (size_t)h * HALF);
    float*  __restrict__ orow = out + (size_t)r * VOCAB;

    // ---- Pass A: batch-load entire half-row slice into registers ----
    float4 v[PER_T];
    #pragma unroll
    for (int j = 0; j < PER_T; j++) {
        int idx = j * NT + tid;
        if (idx < Q4) v[j] = l4[idx];
    }

    // ---- exp in registers + local sum ----
    float s = 0.0f;
    #pragma unroll
    for (int j = 0; j < PER_T; j++) {
        int idx = j * NT + tid;
        if (idx < Q4) {
            float4 e;
            e.x = __expf(fminf(v[j].x, 87.0f));
            e.y = __expf(fminf(v[j].y, 87.0f));
            e.z = __expf(fminf(v[j].z, 87.0f));
            e.w = __expf(fminf(v[j].w, 87.0f));
            v[j] = e;
            s += (e.x + e.y) + (e.z + e.w);
        }
    }
    s = warp_sum(s);
    if (lane == 0) red_sum[wid] = s;
    __syncthreads();
    if (tid < 32) {
        float t = (lane < 16) ? red_sum[lane] : 0.0f;
        t = warp_sum(t);
        if (lane == 0) partial = t;
    }

    // ---- Exchange partial sums across the cluster ----
    cluster.sync();                            // partials visible cluster-wide
    if (tid == 0) {
        const float* peer = cluster.map_shared_rank(&partial, h ^ 1);
        gsum_sh = partial + *peer;
    }
    __syncthreads();
    const float gsum = gsum_sh;

    // ---- Masks & scales ----
    const int p = prev_words[r];
    const bool om = (p <= 88) | ((p >= 91) & (p <= 291));
    const bool cm = (p == 89) | (p == 90) | (p >= 292);
    const float ol = optor_lamda[0];
    const float cl = const_lamda[0];
    const float base = (om ? (1.0f - ol) : 0.0f) + (cm ? (1.0f - cl) : 0.0f);
    const float scale = base / gsum;

    // ---- Pass C: registers -> DRAM, scaled ----
    #pragma unroll
    for (int j = 0; j < PER_T; j++) {
        int idx = j * NT + tid;
        if (idx < Q4) {
            float4 y;
            y.x = v[j].x * scale;
            y.y = v[j].y * scale;
            y.z = v[j].z * scale;
            y.w = v[j].w * scale;
            o4[idx] = y;
        }
    }
    __syncthreads();   // my half's base values ordered before my scatter atomics

    // ---- Scatter (each CTA owns indices in its own half of the row) ----
    const int lo = h * HALF, hi = lo + HALF;
    if (wid == 0) {
        const float t = optor_temp[0];
        const float d = optor_dists[(size_t)r * KNN + lane];
        const float x = -d / t;
        const float mm = warp_max(x);
        const float e  = __expf(x - mm);
        const float ss = warp_sum(e);
        const int idx  = optor_vals[(size_t)r * KNN + lane];
        if (om && idx >= lo && idx < hi) {
            atomicAdd(&orow[idx], ol * e / ss);
        }
    } else if (wid == 1) {
        const float t = const_temp[0];
        const float d = const_dists[(size_t)r * KNN + lane];
        const float x = -d / t;
        const float mm = warp_max(x);
        const float e  = __expf(x - mm);
        const float ss = warp_sum(e);
        const int idx  = const_vals[(size_t)r * KNN + lane];
        if (cm && idx >= lo && idx < hi) {
            atomicAdd(&orow[idx], cl * e / ss);
        }
    }

    // No CTA may exit while its peer could still read its smem (partial).
    cluster.sync();
}

extern "C" void kernel_launch(void* const* d_in, const int* in_sizes, int n_in,
                              void* d_out, int out_size)
{
    const float* logits      = (const float*)d_in[0];
    const int*   optor_vals  = (const int*)  d_in[1];
    const float* optor_dists = (const float*)d_in[2];
    const int*   const_vals  = (const int*)  d_in[3];
    const float* const_dists = (const float*)d_in[4];
    const int*   prev_words  = (const int*)  d_in[5];
    const float* optor_lamda = (const float*)d_in[6];
    const float* const_lamda = (const float*)d_in[7];
    const float* optor_temp  = (const float*)d_in[8];
    const float* const_temp  = (const float*)d_in[9];
    float* out = (float*)d_out;

    const int rows = in_sizes[5];                 // B*S = 1024

    knn_model_kernel<<<rows * 2, NT>>>(
        logits, optor_vals, optor_dists, const_vals, const_dists,
        prev_words, optor_lamda, const_lamda, optor_temp, const_temp, out);
}

// round 5
// speedup vs baseline: 1.4524x; 1.4524x over previous
#include <cuda_runtime.h>
#include <cooperative_groups.h>
#include <math.h>
#include <stdint.h>

namespace cg = cooperative_groups;

#define VOCAB 32000
#define HALF  16000
#define Q4    4000      // float4 per half-row
#define KNN   32
#define NT    512
#define NC    222       // clusters (444 CTAs = 3 per SM)

__device__ __forceinline__ float warp_max(float v) {
    #pragma unroll
    for (int o = 16; o > 0; o >>= 1) v = fmaxf(v, __shfl_xor_sync(0xFFFFFFFFu, v, o));
    return v;
}
__device__ __forceinline__ float warp_sum(float v) {
    #pragma unroll
    for (int o = 16; o > 0; o >>= 1) v += __shfl_xor_sync(0xFFFFFFFFu, v, o);
    return v;
}

__device__ __forceinline__ void mbar_init1(unsigned long long* m) {
    uint32_t a = (uint32_t)__cvta_generic_to_shared(m);
    asm volatile("mbarrier.init.shared.b64 [%0], 1;" :: "r"(a) : "memory");
}
__device__ __forceinline__ void mbar_arrive_peer(unsigned long long* m, uint32_t peer) {
    uint32_t a = (uint32_t)__cvta_generic_to_shared(m);
    asm volatile(
        "{\n\t.reg .b32 r%=;\n\t"
        "mapa.shared::cluster.u32 r%=, %0, %1;\n\t"
        "mbarrier.arrive.release.cluster.shared::cluster.b64 _, [r%=];\n\t}"
        :: "r"(a), "r"(peer) : "memory");
}
__device__ __forceinline__ void mbar_wait(unsigned long long* m, uint32_t parity) {
    uint32_t a = (uint32_t)__cvta_generic_to_shared(m);
    asm volatile(
        "{\n\t.reg .pred P%=;\n\t"
        "W%=:\n\t"
        "mbarrier.try_wait.parity.acquire.cluster.shared::cta.b64 P%=, [%0], %1, 0x989680;\n\t"
        "@P%= bra D%=;\n\t"
        "bra W%=;\n\t"
        "D%=:\n\t}"
        :: "r"(a), "r"(parity) : "memory");
}

__global__ __launch_bounds__(NT, 3) __cluster_dims__(2, 1, 1)
void knn_model_kernel(const float* __restrict__ logits,
                      const int*   __restrict__ optor_vals,
                      const float* __restrict__ optor_dists,
                      const int*   __restrict__ const_vals,
                      const float* __restrict__ const_dists,
                      const int*   __restrict__ prev_words,
                      const float* __restrict__ optor_lamda,
                      const float* __restrict__ const_lamda,
                      const float* __restrict__ optor_temp,
                      const float* __restrict__ const_temp,
                      float*       __restrict__ out,
                      int          rows)
{
    extern __shared__ float buf[];              // HALF floats (62.5 KB)
    __shared__ float red[16];
    __shared__ float partial[2];                // double-buffered exchange slots
    __shared__ float scale_sh;
    __shared__ __align__(8) unsigned long long mbar;

    cg::cluster_group cluster = cg::this_cluster();

    const int cid  = blockIdx.x >> 1;           // cluster id
    const int h    = blockIdx.x & 1;            // half index == cluster rank
    const int tid  = threadIdx.x;
    const int wid  = tid >> 5;
    const int lane = tid & 31;
    const uint32_t peer = (uint32_t)(h ^ 1);

    if (tid == 0) mbar_init1(&mbar);
    cluster.sync();                             // mbar init visible cluster-wide

    const float* peer_partial = cluster.map_shared_rank((const float*)partial, peer);

    float4* __restrict__ b4 = (float4*)buf;

    const float ol = optor_lamda[0];
    const float cl = const_lamda[0];
    const float otp = optor_temp[0];
    const float ctp = const_temp[0];
    const int lo = h * HALF, hi = lo + HALF;

    // ---- prologue: load first task into smem as exp(x), local sum ----
    float s = 0.0f;
    {
        const float4* l4 = (const float4*)(logits + (size_t)cid * VOCAB + (size_t)h * HALF);
        #pragma unroll 4
        for (int i = tid; i < Q4; i += NT) {
            float4 x = l4[i];
            float4 e;
            e.x = __expf(fminf(x.x, 87.0f));
            e.y = __expf(fminf(x.y, 87.0f));
            e.z = __expf(fminf(x.z, 87.0f));
            e.w = __expf(fminf(x.w, 87.0f));
            b4[i] = e;
            s += (e.x + e.y) + (e.z + e.w);
        }
    }

    int k = 0;                                  // task counter (parity source)
    for (int t = cid; t < rows; t += NC, k++) {
        const int slot = k & 1;

        // ---- block-reduce local sum into partial[slot] ----
        float v = warp_sum(s);
        if (lane == 0) red[wid] = v;
        __syncthreads();
        if (tid < 32) {
            float w = (lane < 16) ? red[lane] : 0.0f;
            w = warp_sum(w);
            if (lane == 0) partial[slot] = w;
        }
        __syncthreads();                        // partial[slot] visible before signaling

        // ---- exchange with peer via mbarrier handshake ----
        if (tid == 0) {
            mbar_arrive_peer(&mbar, peer);      // tell peer: my partial[slot] ready
            mbar_wait(&mbar, (uint32_t)slot);   // wait: peer's partial[slot] ready
            const float gsum = partial[slot] + peer_partial[slot];

            const int p = prev_words[t];
            const bool om = (p <= 88) | ((p >= 91) & (p <= 291));
            const bool cm = (p == 89) | (p == 90) | (p >= 292);
            const float base = (om ? (1.0f - ol) : 0.0f) + (cm ? (1.0f - cl) : 0.0f);
            scale_sh = base / gsum;
        }
        __syncthreads();
        const float scale = scale_sh;

        // ---- fused: write task t (smem -> DRAM), load task t+NC (DRAM -> smem) ----
        float4* o4 = (float4*)(out + (size_t)t * VOCAB + (size_t)h * HALF);
        const int tn = t + NC;
        float ns = 0.0f;
        if (tn < rows) {
            const float4* n4 = (const float4*)(logits + (size_t)tn * VOCAB + (size_t)h * HALF);
            #pragma unroll 2
            for (int i = tid; i < Q4; i += NT) {
                float4 e = b4[i];               // exp of task t
                float4 x = n4[i];               // next row (LDG issues early)
                float4 y;
                y.x = e.x * scale; y.y = e.y * scale;
                y.z = e.z * scale; y.w = e.w * scale;
                o4[i] = y;
                float4 ee;
                ee.x = __expf(fminf(x.x, 87.0f));
                ee.y = __expf(fminf(x.y, 87.0f));
                ee.z = __expf(fminf(x.z, 87.0f));
                ee.w = __expf(fminf(x.w, 87.0f));
                b4[i] = ee;                     // same thread, same slot: no hazard
                ns += (ee.x + ee.y) + (ee.z + ee.w);
            }
        } else {
            #pragma unroll 4
            for (int i = tid; i < Q4; i += NT) {
                float4 e = b4[i];
                float4 y;
                y.x = e.x * scale; y.y = e.y * scale;
                y.z = e.z * scale; y.w = e.w * scale;
                o4[i] = y;
            }
        }
        __syncthreads();                        // task t's base values written before atomics

        // ---- scatter for task t (warp 0: optor, warp 1: const) ----
        float* orow = out + (size_t)t * VOCAB;
        if (wid == 0) {
            const int p = prev_words[t];
            const bool om = (p <= 88) | ((p >= 91) & (p <= 291));
            const float d = optor_dists[(size_t)t * KNN + lane];
            const float x = -d / otp;
            const float mm = warp_max(x);
            const float e  = __expf(x - mm);
            const float ss = warp_sum(e);
            const int idx  = optor_vals[(size_t)t * KNN + lane];
            if (om && idx >= lo && idx < hi) atomicAdd(&orow[idx], ol * e / ss);
        } else if (wid == 1) {
            const int p = prev_words[t];
            const bool cm = (p == 89) | (p == 90) | (p >= 292);
            const float d = const_dists[(size_t)t * KNN + lane];
            const float x = -d / ctp;
            const float mm = warp_max(x);
            const float e  = __expf(x - mm);
            const float ss = warp_sum(e);
            const int idx  = const_vals[(size_t)t * KNN + lane];
            if (cm && idx >= lo && idx < hi) atomicAdd(&orow[idx], cl * e / ss);
        }

        s = ns;
    }

    cluster.sync();                             // peer may still read my smem
}

extern "C" void kernel_launch(void* const* d_in, const int* in_sizes, int n_in,
                              void* d_out, int out_size)
{
    const float* logits      = (const float*)d_in[0];
    const int*   optor_vals  = (const int*)  d_in[1];
    const float* optor_dists = (const float*)d_in[2];
    const int*   const_vals  = (const int*)  d_in[3];
    const float* const_dists = (const float*)d_in[4];
    const int*   prev_words  = (const int*)  d_in[5];
    const float* optor_lamda = (const float*)d_in[6];
    const float* const_lamda = (const float*)d_in[7];
    const float* optor_temp  = (const float*)d_in[8];
    const float* const_temp  = (const float*)d_in[9];
    float* out = (float*)d_out;

    const int rows = in_sizes[5];                 // B*S = 1024
    const int smem = HALF * (int)sizeof(float);   // 64000 bytes per CTA

    cudaFuncSetAttribute(knn_model_kernel,
                         cudaFuncAttributeMaxDynamicSharedMemorySize, smem);

    knn_model_kernel<<<NC * 2, NT, smem>>>(
        logits, optor_vals, optor_dists, const_vals, const_dists,
        prev_words, optor_lamda, const_lamda, optor_temp, const_temp, out, rows);
}

// round 6
// speedup vs baseline: 1.5254x; 1.0503x over previous
#include <cuda_runtime.h>
#include <math.h>

#define VOCAB 32000
#define Q4    8000     // float4 per row
#define KNN   32
#define NT    512

__device__ __forceinline__ float warp_max(float v) {
    #pragma unroll
    for (int o = 16; o > 0; o >>= 1) v = fmaxf(v, __shfl_xor_sync(0xFFFFFFFFu, v, o));
    return v;
}
__device__ __forceinline__ float warp_sum(float v) {
    #pragma unroll
    for (int o = 16; o > 0; o >>= 1) v += __shfl_xor_sync(0xFFFFFFFFu, v, o);
    return v;
}

__device__ __forceinline__ float4 ldlu4(const float4* p) {
    float4 r;
    asm volatile("ld.global.lu.v4.f32 {%0,%1,%2,%3}, [%4];"
                 : "=f"(r.x), "=f"(r.y), "=f"(r.z), "=f"(r.w) : "l"(p));
    return r;
}
__device__ __forceinline__ void stcs4(float4* p, float4 v) {
    asm volatile("st.global.cs.v4.f32 [%0], {%1,%2,%3,%4};"
                 :: "l"(p), "f"(v.x), "f"(v.y), "f"(v.z), "f"(v.w) : "memory");
}

__global__ __launch_bounds__(NT, 4)
void knn_model_kernel(const float* __restrict__ logits,
                      const int*   __restrict__ optor_vals,
                      const float* __restrict__ optor_dists,
                      const int*   __restrict__ const_vals,
                      const float* __restrict__ const_dists,
                      const int*   __restrict__ prev_words,
                      const float* __restrict__ optor_lamda,
                      const float* __restrict__ const_lamda,
                      const float* __restrict__ optor_temp,
                      const float* __restrict__ const_temp,
                      float*       __restrict__ out)
{
    __shared__ float red[16];
    __shared__ float scale_sh;

    const int r    = blockIdx.x;              // one row per CTA
    const int tid  = threadIdx.x;
    const int wid  = tid >> 5;
    const int lane = tid & 31;

    const float4* __restrict__ l4 = (const float4*)(logits + (size_t)r * VOCAB);
    float4* __restrict__ o4 = (float4*)(out + (size_t)r * VOCAB);
    float*  __restrict__ orow = out + (size_t)r * VOCAB;

    // ---- Pass A: pure read (populates L2), exp, block sum ----
    float s = 0.0f;
    #pragma unroll 4
    for (int i = tid; i < Q4; i += NT) {
        float4 x = l4[i];
        s += __expf(fminf(x.x, 87.0f)) + __expf(fminf(x.y, 87.0f))
           + __expf(fminf(x.z, 87.0f)) + __expf(fminf(x.w, 87.0f));
    }
    s = warp_sum(s);
    if (lane == 0) red[wid] = s;
    __syncthreads();
    if (tid < 32) {
        float v = (lane < 16) ? red[lane] : 0.0f;
        v = warp_sum(v);
        if (lane == 0) {
            const int p = prev_words[r];
            const bool om = (p <= 88) | ((p >= 91) & (p <= 291));
            const bool cm = (p == 89) | (p == 90) | (p >= 292);
            const float ol = optor_lamda[0];
            const float cl = const_lamda[0];
            const float base = (om ? (1.0f - ol) : 0.0f) + (cm ? (1.0f - cl) : 0.0f);
            scale_sh = base / v;
        }
    }
    __syncthreads();
    const float scale = scale_sh;

    // ---- Pass C: re-read row (L2 hit, last-use), exp, scale, streaming store ----
    #pragma unroll 4
    for (int i = tid; i < Q4; i += NT) {
        float4 x = ldlu4(&l4[i]);
        float4 y;
        y.x = __expf(fminf(x.x, 87.0f)) * scale;
        y.y = __expf(fminf(x.y, 87.0f)) * scale;
        y.z = __expf(fminf(x.z, 87.0f)) * scale;
        y.w = __expf(fminf(x.w, 87.0f)) * scale;
        stcs4(&o4[i], y);
    }
    __syncthreads();   // all base stores issued before scatter atomics

    // ---- Scatter: warp 0 = optor, warp 1 = const ----
    if (wid == 0) {
        const int p = prev_words[r];
        const bool om = (p <= 88) | ((p >= 91) & (p <= 291));
        const float t = optor_temp[0];
        const float d = optor_dists[(size_t)r * KNN + lane];
        const float x = -d / t;
        const float mm = warp_max(x);
        const float e  = __expf(x - mm);
        const float ss = warp_sum(e);
        if (om) atomicAdd(&orow[optor_vals[(size_t)r * KNN + lane]],
                          optor_lamda[0] * e / ss);
    } else if (wid == 1) {
        const int p = prev_words[r];
        const bool cm = (p == 89) | (p == 90) | (p >= 292);
        const float t = const_temp[0];
        const float d = const_dists[(size_t)r * KNN + lane];
        const float x = -d / t;
        const float mm = warp_max(x);
        const float e  = __expf(x - mm);
        const float ss = warp_sum(e);
        if (cm) atomicAdd(&orow[const_vals[(size_t)r * KNN + lane]],
                          const_lamda[0] * e / ss);
    }
}

extern "C" void kernel_launch(void* const* d_in, const int* in_sizes, int n_in,
                              void* d_out, int out_size)
{
    const float* logits      = (const float*)d_in[0];
    const int*   optor_vals  = (const int*)  d_in[1];
    const float* optor_dists = (const float*)d_in[2];
    const int*   const_vals  = (const int*)  d_in[3];
    const float* const_dists = (const float*)d_in[4];
    const int*   prev_words  = (const int*)  d_in[5];
    const float* optor_lamda = (const float*)d_in[6];
    const float* const_lamda = (const float*)d_in[7];
    const float* optor_temp  = (const float*)d_in[8];
    const float* const_temp  = (const float*)d_in[9];
    float* out = (float*)d_out;

    const int rows = in_sizes[5];                 // B*S = 1024

    knn_model_kernel<<<rows, NT>>>(
        logits, optor_vals, optor_dists, const_vals, const_dists,
        prev_words, optor_lamda, const_lamda, optor_temp, const_temp, out);
}